// round 14
// baseline (speedup 1.0000x reference)
#include <cuda_runtime.h>
#include <cuda_fp16.h>
#include <math.h>
#include <stdint.h>

// Problem constants (fixed shapes)
#define NN 50000
#define EE 200000
#define RR 3
#define FF 128
#define HH 256
#define PP 100000
#define NPAIRS (RR*EE + PP)   // 700000
#define NBINS (RR*NN)         // 150000

// scratch layout (float slots) — [zeroed region | persistent region]
#define OFF_SC_OUT 0ull                 // 150000 raw out-degree counts
#define OFF_SC_IN  150000ull            // 150000 raw in-degree counts
#define OFF_CURSOR 300000ull            // 150016 ints
#define ZERO_FLOATS 450016ull
#define OFF_OFFSET 450016ull            // 150016 ints
#define OFF_BLKSUM 600032ull            // 256 ints
#define OFF_EDG    600288ull            // 600000 x uint2 {src, scale} = 1,200,000 slots
#define OFF_XH     1800288ull           // half[N][128] = 3,200,000 slots
#define OFF_AGGH   5000288ull           // half[N][384] = 9,600,000 slots ; reused as z
#define OFF_H1H    14600288ull          // half[N][256] = 6,400,000 slots
#define OFF_U      21000288ull
#define OFF_V      21050288ull
#define OFF_BS1    21100288ull          // 256 floats
#define OFF_BS2    21100544ull          // 128 floats
#define OFF_BT1H   21100672ull          // half[256][384] = 49152 slots
#define OFF_BT2H   21149824ull          // half[384][256] = 49152 slots
#define SCRATCH_TOTAL 21198976ull

__device__ float g_scratch[SCRATCH_TOTAL];

// ================================================================ fused prep: zero + weight/bias pack + x->half
#define ZERO4 (ZERO_FLOATS / 4)                    // 112504
#define PACKN (2 * HH * RR * FF + HH + FF)         // 196992
#define XHN   (NN * FF / 8)                        // 800000
#define PREPN (ZERO4 + PACKN + XHN)

__global__ void prep_kernel(const float* __restrict__ W1, const float* __restrict__ W2,
                            const float* __restrict__ b1, const float* __restrict__ b2,
                            const float* __restrict__ x) {
    int idx = blockIdx.x * blockDim.x + threadIdx.x;
    if (idx < ZERO4) {
        reinterpret_cast<float4*>(g_scratch)[idx] = make_float4(0.f, 0.f, 0.f, 0.f);
        return;
    }
    idx -= ZERO4;
    if (idx < PACKN) {
        int i = idx;
        if (i < HH * RR * FF) {
            int h = i / (RR * FF);
            int k = i - h * (RR * FF);
            __half* bt = reinterpret_cast<__half*>(&g_scratch[OFF_BT1H]);
            bt[(size_t)h * (RR * FF) + k] = __float2half(W1[(size_t)k * HH + h]);
        } else if (i < 2 * HH * RR * FF) {
            int j = i - HH * RR * FF;
            int rf = j / HH;
            int h = j - rf * HH;
            int r = rf >> 7;
            int f = rf & 127;
            __half* bt = reinterpret_cast<__half*>(&g_scratch[OFF_BT2H]);
            bt[(size_t)rf * HH + h] = __float2half(W2[(size_t)r * HH * FF + (size_t)h * FF + f]);
        } else {
            int t = i - 2 * HH * RR * FF;
            if (t < HH) {
                g_scratch[OFF_BS1 + t] = b1[t] + b1[HH + t] + b1[2 * HH + t];
            } else {
                int h = t - HH;
                g_scratch[OFF_BS2 + h] = b2[h] + b2[FF + h] + b2[2 * FF + h];
            }
        }
        return;
    }
    idx -= PACKN;
    if (idx < XHN) {
        const float4* x4 = reinterpret_cast<const float4*>(x);
        float4 a = x4[2 * idx];
        float4 b = x4[2 * idx + 1];
        __half2 h0 = __floats2half2_rn(a.x, a.y);
        __half2 h1 = __floats2half2_rn(a.z, a.w);
        __half2 h2 = __floats2half2_rn(b.x, b.y);
        __half2 h3 = __floats2half2_rn(b.z, b.w);
        uint4 o;
        o.x = *reinterpret_cast<unsigned*>(&h0);
        o.y = *reinterpret_cast<unsigned*>(&h1);
        o.z = *reinterpret_cast<unsigned*>(&h2);
        o.w = *reinterpret_cast<unsigned*>(&h3);
        reinterpret_cast<uint4*>(&g_scratch[OFF_XH])[idx] = o;
    }
}

// ================================================================ degrees
__global__ void deg_kernel(const int* __restrict__ ei) {
    int i = blockIdx.x * blockDim.x + threadIdx.x;
    if (i >= RR * EE) return;
    int r = i / EE, e = i - r * EE;
    int src = ei[(size_t)r * 2 * EE + e];
    int dst = ei[(size_t)r * 2 * EE + EE + e];
    atomicAdd(&g_scratch[OFF_SC_OUT + (size_t)r * NN + src], 1.f);
    atomicAdd(&g_scratch[OFF_SC_IN  + (size_t)r * NN + dst], 1.f);
}

// ================================================================ scan (3 kernels, R10-proven)
#define SCAN_B 1024
#define SCAN_NBLK ((NBINS + SCAN_B - 1) / SCAN_B)   // 147

__global__ void scanA_kernel() {
    __shared__ int sm[SCAN_B];
    int tid = threadIdx.x;
    int i = blockIdx.x * SCAN_B + tid;
    int v = (i < NBINS) ? (int)g_scratch[OFF_SC_IN + i] : 0;
    sm[tid] = v;
    __syncthreads();
    for (int off = 1; off < SCAN_B; off <<= 1) {
        int t = (tid >= off) ? sm[tid - off] : 0;
        __syncthreads();
        sm[tid] += t;
        __syncthreads();
    }
    if (i < NBINS)
        reinterpret_cast<int*>(g_scratch)[OFF_OFFSET + i] = sm[tid] - v;
    if (tid == SCAN_B - 1)
        reinterpret_cast<int*>(g_scratch)[OFF_BLKSUM + blockIdx.x] = sm[tid];
}

__global__ void scanB_kernel() {
    __shared__ int sm[256];
    int tid = threadIdx.x;
    int* bs = reinterpret_cast<int*>(g_scratch) + OFF_BLKSUM;
    int v = (tid < SCAN_NBLK) ? bs[tid] : 0;
    sm[tid] = v;
    __syncthreads();
    for (int off = 1; off < 256; off <<= 1) {
        int t = (tid >= off) ? sm[tid - off] : 0;
        __syncthreads();
        sm[tid] += t;
        __syncthreads();
    }
    if (tid < SCAN_NBLK) bs[tid] = sm[tid] - v;
}

__global__ void scanC_kernel() {
    int i = blockIdx.x * blockDim.x + threadIdx.x;
    if (i >= NBINS) return;
    int* ip = reinterpret_cast<int*>(g_scratch);
    ip[OFF_OFFSET + i] += ip[OFF_BLKSUM + i / SCAN_B];
}

// ================================================================ edge placement: CSR by (r,dst), rsqrt-scales inline
__global__ void place_kernel(const int* __restrict__ ei) {
    int i = blockIdx.x * blockDim.x + threadIdx.x;
    if (i >= RR * EE) return;
    int r = i / EE, e = i - r * EE;
    int src = ei[(size_t)r * 2 * EE + e];
    int dst = ei[(size_t)r * 2 * EE + EE + e];
    float dout = g_scratch[OFF_SC_OUT + (size_t)r * NN + src];
    float din  = g_scratch[OFF_SC_IN  + (size_t)r * NN + dst];
    float s = rsqrtf(fmaxf(dout, 1.f)) * rsqrtf(fmaxf(din, 1.f));
    int bin = r * NN + dst;
    int* ip = reinterpret_cast<int*>(g_scratch);
    int pos = ip[OFF_OFFSET + bin] + atomicAdd(&ip[OFF_CURSOR + bin], 1);
    uint2* edg = reinterpret_cast<uint2*>(&g_scratch[OFF_EDG]);
    uint2 rec;
    rec.x = (unsigned)src;
    rec.y = __float_as_uint(s);
    edg[pos] = rec;
}

// ================================================================ gather helper: 8-feature fma from uint4 of halves
__device__ __forceinline__ void gfma8(float* acc, float c, const uint4& w) {
    const __half2* h = reinterpret_cast<const __half2*>(&w);
    #pragma unroll
    for (int q = 0; q < 4; q++) {
        float2 f = __half22float2(h[q]);
        acc[2 * q]     = fmaf(c, f.x, acc[2 * q]);
        acc[2 * q + 1] = fmaf(c, f.y, acc[2 * q + 1]);
    }
}

// ================================================================ gather layer 1 — half-warp dual-edge groups
__global__ void gather1_kernel() {
    int dst = (blockIdx.x * blockDim.x + threadIdx.x) >> 5;
    int lane = threadIdx.x & 31;
    if (dst >= NN) return;
    int g = lane >> 4;       // edge group 0/1
    int l16 = lane & 15;     // feature chunk: halves l16*8..+7
    const int* ip = reinterpret_cast<const int*>(g_scratch);
    const uint2* edg = reinterpret_cast<const uint2*>(&g_scratch[OFF_EDG]);
    const __half* xh = reinterpret_cast<const __half*>(&g_scratch[OFF_XH]);
    __half* aggh = reinterpret_cast<__half*>(&g_scratch[OFF_AGGH]);
    #pragma unroll
    for (int r = 0; r < RR; r++) {
        int bin = r * NN + dst;
        int st = ip[OFF_OFFSET + bin];
        int cnt = ip[OFF_CURSOR + bin];
        float a0[8] = {0.f, 0.f, 0.f, 0.f, 0.f, 0.f, 0.f, 0.f};
        float a1[8] = {0.f, 0.f, 0.f, 0.f, 0.f, 0.f, 0.f, 0.f};
        int p = 0;
        for (; p + 4 <= cnt; p += 4) {
            uint2 e0 = edg[st + p + g];
            uint2 e1 = edg[st + p + g + 2];
            uint4 w0 = *reinterpret_cast<const uint4*>(xh + (size_t)e0.x * FF + l16 * 8);
            uint4 w1 = *reinterpret_cast<const uint4*>(xh + (size_t)e1.x * FF + l16 * 8);
            gfma8(a0, __uint_as_float(e0.y), w0);
            gfma8(a1, __uint_as_float(e1.y), w1);
        }
        if (p + g < cnt) {
            uint2 e0 = edg[st + p + g];
            uint4 w0 = *reinterpret_cast<const uint4*>(xh + (size_t)e0.x * FF + l16 * 8);
            gfma8(a0, __uint_as_float(e0.y), w0);
        }
        if (p + g + 2 < cnt) {
            uint2 e1 = edg[st + p + g + 2];
            uint4 w1 = *reinterpret_cast<const uint4*>(xh + (size_t)e1.x * FF + l16 * 8);
            gfma8(a1, __uint_as_float(e1.y), w1);
        }
        #pragma unroll
        for (int q = 0; q < 8; q++) {
            a0[q] += a1[q];
            a0[q] += __shfl_xor_sync(0xffffffffu, a0[q], 16);
        }
        if (g == 0) {
            __half2 h0 = __floats2half2_rn(a0[0], a0[1]);
            __half2 h1 = __floats2half2_rn(a0[2], a0[3]);
            __half2 h2 = __floats2half2_rn(a0[4], a0[5]);
            __half2 h3 = __floats2half2_rn(a0[6], a0[7]);
            uint4 o;
            o.x = *reinterpret_cast<unsigned*>(&h0);
            o.y = *reinterpret_cast<unsigned*>(&h1);
            o.z = *reinterpret_cast<unsigned*>(&h2);
            o.w = *reinterpret_cast<unsigned*>(&h3);
            *reinterpret_cast<uint4*>(aggh + (size_t)dst * 384 + r * FF + l16 * 8) = o;
        }
    }
}

// ================================================================ gather layer 2 + uv — half-warp dual-edge groups
__global__ void gather2_uv_kernel(const float* __restrict__ Wlin) {
    int dst = (blockIdx.x * blockDim.x + threadIdx.x) >> 5;
    int lane = threadIdx.x & 31;
    if (dst >= NN) return;
    int g = lane >> 4;
    int l16 = lane & 15;
    const int* ip = reinterpret_cast<const int*>(g_scratch);
    const uint2* edg = reinterpret_cast<const uint2*>(&g_scratch[OFF_EDG]);
    const __half* zh = reinterpret_cast<const __half*>(&g_scratch[OFF_AGGH]);
    float a0[8] = {0.f, 0.f, 0.f, 0.f, 0.f, 0.f, 0.f, 0.f};
    float a1[8] = {0.f, 0.f, 0.f, 0.f, 0.f, 0.f, 0.f, 0.f};
    #pragma unroll
    for (int r = 0; r < RR; r++) {
        int bin = r * NN + dst;
        int st = ip[OFF_OFFSET + bin];
        int cnt = ip[OFF_CURSOR + bin];
        int p = 0;
        for (; p + 4 <= cnt; p += 4) {
            uint2 e0 = edg[st + p + g];
            uint2 e1 = edg[st + p + g + 2];
            uint4 w0 = *reinterpret_cast<const uint4*>(zh + (size_t)e0.x * 384 + r * FF + l16 * 8);
            uint4 w1 = *reinterpret_cast<const uint4*>(zh + (size_t)e1.x * 384 + r * FF + l16 * 8);
            gfma8(a0, __uint_as_float(e0.y), w0);
            gfma8(a1, __uint_as_float(e1.y), w1);
        }
        if (p + g < cnt) {
            uint2 e0 = edg[st + p + g];
            uint4 w0 = *reinterpret_cast<const uint4*>(zh + (size_t)e0.x * 384 + r * FF + l16 * 8);
            gfma8(a0, __uint_as_float(e0.y), w0);
        }
        if (p + g + 2 < cnt) {
            uint2 e1 = edg[st + p + g + 2];
            uint4 w1 = *reinterpret_cast<const uint4*>(zh + (size_t)e1.x * 384 + r * FF + l16 * 8);
            gfma8(a1, __uint_as_float(e1.y), w1);
        }
    }
    #pragma unroll
    for (int q = 0; q < 8; q++) {
        a0[q] += a1[q];
        a0[q] += __shfl_xor_sync(0xffffffffu, a0[q], 16);
    }
    // epilogue: +bias, /3, relu, dot with Wlin halves (features l16*8..+7)
    const float inv3 = (1.f / 3.f);
    float4 bbA = *reinterpret_cast<const float4*>(&g_scratch[OFF_BS2 + l16 * 8]);
    float4 bbB = *reinterpret_cast<const float4*>(&g_scratch[OFF_BS2 + l16 * 8 + 4]);
    float bs[8] = {bbA.x, bbA.y, bbA.z, bbA.w, bbB.x, bbB.y, bbB.z, bbB.w};
    #pragma unroll
    for (int q = 0; q < 8; q++)
        a0[q] = fmaxf((a0[q] + bs[q]) * inv3, 0.f);
    float4 wlA = *reinterpret_cast<const float4*>(Wlin + l16 * 8);
    float4 wlB = *reinterpret_cast<const float4*>(Wlin + l16 * 8 + 4);
    float4 whA = *reinterpret_cast<const float4*>(Wlin + FF + l16 * 8);
    float4 whB = *reinterpret_cast<const float4*>(Wlin + FF + l16 * 8 + 4);
    float wl[8] = {wlA.x, wlA.y, wlA.z, wlA.w, wlB.x, wlB.y, wlB.z, wlB.w};
    float wh[8] = {whA.x, whA.y, whA.z, whA.w, whB.x, whB.y, whB.z, whB.w};
    float su = 0.f, sv = 0.f;
    #pragma unroll
    for (int q = 0; q < 8; q++) {
        su = fmaf(a0[q], wl[q], su);
        sv = fmaf(a0[q], wh[q], sv);
    }
    #pragma unroll
    for (int o = 8; o > 0; o >>= 1) {
        su += __shfl_xor_sync(0xffffffffu, su, o);
        sv += __shfl_xor_sync(0xffffffffu, sv, o);
    }
    if (lane == 0) {
        g_scratch[OFF_U + dst] = su;
        g_scratch[OFF_V + dst] = sv;
    }
}

// ================================================================ fp16 tensor-core GEMM
// BM=128, BN=128, BK=32; 256 threads; cp.async double-buffered; LDSM fragments
#define BM 128
#define BN 128
#define BK 32
#define BKP 40   // +8 halves pad: 80B row stride -> conflict-free LDSM phases

__device__ __forceinline__ void mma_fp16(float* d, const unsigned* a, const unsigned* b) {
    asm volatile("mma.sync.aligned.m16n8k16.row.col.f32.f16.f16.f32 "
                 "{%0,%1,%2,%3}, {%4,%5,%6,%7}, {%8,%9}, {%0,%1,%2,%3};"
                 : "+f"(d[0]), "+f"(d[1]), "+f"(d[2]), "+f"(d[3])
                 : "r"(a[0]), "r"(a[1]), "r"(a[2]), "r"(a[3]),
                   "r"(b[0]), "r"(b[1]));
}

__device__ __forceinline__ void ldsm_x4(unsigned* r, uint32_t addr) {
    asm volatile("ldmatrix.sync.aligned.m8n8.x4.shared.b16 {%0,%1,%2,%3}, [%4];"
                 : "=r"(r[0]), "=r"(r[1]), "=r"(r[2]), "=r"(r[3]) : "r"(addr));
}

__device__ __forceinline__ uint32_t smem_cast(const void* p) {
    uint32_t a;
    asm("{ .reg .u64 t; cvta.to.shared.u64 t, %1; cvt.u32.u64 %0, t; }" : "=r"(a) : "l"(p));
    return a;
}

__device__ __forceinline__ void cp_async16(uint32_t dst, const void* src, int src_bytes) {
    asm volatile("cp.async.ca.shared.global [%0], [%1], 16, %2;"
                 :: "r"(dst), "l"(src), "r"(src_bytes) : "memory");
}
#define CP_COMMIT() asm volatile("cp.async.commit_group;" ::: "memory")
#define CP_WAIT1()  asm volatile("cp.async.wait_group 1;" ::: "memory")
#define CP_WAIT0()  asm volatile("cp.async.wait_group 0;" ::: "memory")

__global__ __launch_bounds__(256) void gemm_fp16_kernel(
    const __half* __restrict__ A, const __half* __restrict__ Bt,
    const float* __restrict__ bias, __half* __restrict__ C,
    int M, int K, int Ncol, int doRelu, float scale)
{
    __shared__ __half As[2][BM][BKP];
    __shared__ __half Bs[2][BN][BKP];

    int tid = threadIdx.x;
    int warp = tid >> 5;
    int lane = tid & 31;
    int wr = warp >> 1;        // m offset 32*wr
    int wc = warp & 1;         // n offset 64*wc
    int bm = blockIdx.y * BM, bn = blockIdx.x * BN;
    int tg = lane >> 2;
    int tq = lane & 3;

    // LDSM per-lane addressing: quad q covers rows +((q&1)*8), cols +((q>>1)*8)
    int quad = lane >> 3;
    int ldrow = (lane & 7) + ((quad & 1) << 3);
    int ldcol = (quad >> 1) << 3;

    float acc[2][8][4];
    #pragma unroll
    for (int i = 0; i < 2; i++)
        #pragma unroll
        for (int j = 0; j < 8; j++)
            #pragma unroll
            for (int q = 0; q < 4; q++) acc[i][j][q] = 0.f;

    uint32_t as_base = smem_cast(&As[0][0][0]);
    uint32_t bs_base = smem_cast(&Bs[0][0][0]);
    const uint32_t BUFB = BM * BKP * 2;

    int nT = K / BK;

    #define LOAD_TILE(k0, buf) do {                                              \
        _Pragma("unroll")                                                        \
        for (int it = 0; it < 2; it++) {                                         \
            int ch = tid + it * 256;                                             \
            int row = ch >> 2, c8 = ch & 3;                                      \
            int m = bm + row;                                                    \
            int mc = (m < M) ? m : 0;                                            \
            cp_async16(as_base + (buf) * BUFB + row * (BKP * 2) + c8 * 16,       \
                       A + (size_t)mc * K + (k0) + c8 * 8, (m < M) ? 16 : 0);    \
        }                                                                        \
        _Pragma("unroll")                                                        \
        for (int it = 0; it < 2; it++) {                                         \
            int ch = tid + it * 256;                                             \
            int row = ch >> 2, c8 = ch & 3;                                      \
            cp_async16(bs_base + (buf) * BUFB + row * (BKP * 2) + c8 * 16,       \
                       Bt + (size_t)(bn + row) * K + (k0) + c8 * 8, 16);         \
        }                                                                        \
    } while (0)

    LOAD_TILE(0, 0);
    CP_COMMIT();

    for (int t = 0; t < nT; t++) {
        int buf = t & 1;
        if (t + 1 < nT) {
            LOAD_TILE((t + 1) * BK, buf ^ 1);
            CP_COMMIT();
            CP_WAIT1();
        } else {
            CP_WAIT0();
        }
        __syncthreads();

        #pragma unroll
        for (int kk = 0; kk < BK; kk += 16) {
            unsigned af[2][4], bf[8][2];
            #pragma unroll
            for (int i = 0; i < 2; i++) {
                int mb = wr * 32 + i * 16;
                uint32_t addr = as_base + (uint32_t)buf * BUFB
                              + (uint32_t)((mb + ldrow) * (BKP * 2) + (kk + ldcol) * 2);
                ldsm_x4(af[i], addr);
            }
            #pragma unroll
            for (int j2 = 0; j2 < 4; j2++) {
                int nb = wc * 64 + j2 * 16;
                uint32_t addr = bs_base + (uint32_t)buf * BUFB
                              + (uint32_t)((nb + ldrow) * (BKP * 2) + (kk + ldcol) * 2);
                unsigned tb[4];
                ldsm_x4(tb, addr);
                bf[2 * j2][0]     = tb[0];
                bf[2 * j2 + 1][0] = tb[1];
                bf[2 * j2][1]     = tb[2];
                bf[2 * j2 + 1][1] = tb[3];
            }
            #pragma unroll
            for (int i = 0; i < 2; i++)
                #pragma unroll
                for (int j = 0; j < 8; j++)
                    mma_fp16(acc[i][j], af[i], bf[j]);
        }
        __syncthreads();
    }

    #pragma unroll
    for (int i = 0; i < 2; i++) {
        #pragma unroll
        for (int j = 0; j < 8; j++) {
            int col = bn + wc * 64 + j * 8 + tq * 2;
            float b0 = 0.f, b1 = 0.f;
            if (bias) { b0 = bias[col]; b1 = bias[col + 1]; }
            #pragma unroll
            for (int h = 0; h < 2; h++) {
                int row = bm + wr * 32 + i * 16 + tg + h * 8;
                if (row < M) {
                    float o0 = (acc[i][j][2 * h + 0] + b0) * scale;
                    float o1 = (acc[i][j][2 * h + 1] + b1) * scale;
                    if (doRelu) { o0 = fmaxf(o0, 0.f); o1 = fmaxf(o1, 0.f); }
                    *reinterpret_cast<__half2*>(C + (size_t)row * Ncol + col) =
                        __floats2half2_rn(o0, o1);
                }
            }
        }
    }
}

// ================================================================ pair head
__global__ void pairs_kernel(const int* __restrict__ ei, const int* __restrict__ np,
                             const float* __restrict__ blin, float* __restrict__ out) {
    int i = blockIdx.x * blockDim.x + threadIdx.x;
    if (i >= NPAIRS) return;
    int src, dst;
    if (i < RR * EE) {
        int r = i / EE, e = i - r * EE;
        src = ei[(size_t)r * 2 * EE + e];
        dst = ei[(size_t)r * 2 * EE + EE + e];
    } else {
        int j = i - RR * EE;
        src = np[2 * j];
        dst = np[2 * j + 1];
    }
    float z = g_scratch[OFF_U + src] + g_scratch[OFF_V + dst] + blin[0];
    out[i] = 1.f / (1.f + expf(-z));
}

// ================================================================ launch
extern "C" void kernel_launch(void* const* d_in, const int* in_sizes, int n_in,
                              void* d_out, int out_size) {
    const float* x    = (const float*)d_in[0];
    const int*   ei   = (const int*)  d_in[1];
    const int*   np   = (const int*)  d_in[2];
    const float* W1   = (const float*)d_in[3];
    const float* b1   = (const float*)d_in[4];
    const float* W2   = (const float*)d_in[5];
    const float* b2   = (const float*)d_in[6];
    const float* Wlin = (const float*)d_in[7];
    const float* blin = (const float*)d_in[8];
    float* out = (float*)d_out;

    void* base = nullptr;
    cudaGetSymbolAddress(&base, g_scratch);
    float* fb = (float*)base;
    __half* aggh = (__half*)(fb + OFF_AGGH);
    __half* h1h  = (__half*)(fb + OFF_H1H);
    __half* bt1h = (__half*)(fb + OFF_BT1H);
    __half* bt2h = (__half*)(fb + OFF_BT2H);
    float* bs1   = fb + OFF_BS1;

    // 1. fused prep: zero + pack + x->half
    prep_kernel<<<(PREPN + 255) / 256, 256>>>(W1, W2, b1, b2, x);
    // 2. degrees
    deg_kernel<<<(RR * EE + 255) / 256, 256>>>(ei);
    // 3. CSR offsets (3-kernel scan)
    scanA_kernel<<<SCAN_NBLK, SCAN_B>>>();
    scanB_kernel<<<1, 256>>>();
    scanC_kernel<<<(NBINS + 255) / 256, 256>>>();
    // 4. edge placement (rsqrt folded)
    place_kernel<<<(RR * EE + 255) / 256, 256>>>(ei);
    // 5. layer-1 gather (half-warp dual-edge)
    gather1_kernel<<<(NN * 32 + 255) / 256, 256>>>();
    // 6. GEMM1: h1 = relu((agg @ W1 + bs1)/3)
    gemm_fp16_kernel<<<dim3(HH / BN, (NN + BM - 1) / BM), 256>>>(
        aggh, bt1h, bs1, h1h, NN, RR * FF, HH, 1, 1.f / 3.f);
    // 7. GEMM2: z = h1 @ W2P -> reuse aggh
    gemm_fp16_kernel<<<dim3((RR * FF) / BN, (NN + BM - 1) / BM), 256>>>(
        h1h, bt2h, nullptr, aggh, NN, HH, RR * FF, 0, 1.f);
    // 8. layer-2 gather + u/v (half-warp dual-edge)
    gather2_uv_kernel<<<(NN * 32 + 255) / 256, 256>>>(Wlin);
    // 9. pair outputs
    pairs_kernel<<<(NPAIRS + 255) / 256, 256>>>(ei, np, blin, out);
}

// round 15
// speedup vs baseline: 1.0572x; 1.0572x over previous
#include <cuda_runtime.h>
#include <cuda_fp16.h>
#include <math.h>
#include <stdint.h>

// Problem constants (fixed shapes)
#define NN 50000
#define EE 200000
#define RR 3
#define FF 128
#define HH 256
#define PP 100000
#define NPAIRS (RR*EE + PP)   // 700000
#define NBINS (RR*NN)         // 150000

// scratch layout (float slots) — [zeroed region | persistent region]
#define OFF_SC_OUT 0ull                 // 150000 raw out-degree counts
#define OFF_SC_IN  150000ull            // 150000 raw in-degree counts
#define OFF_CURSOR 300000ull            // 150016 ints
#define ZERO_FLOATS 450016ull
#define OFF_OFFSET 450016ull            // 150016 ints
#define OFF_BLKSUM 600032ull            // 256 ints
#define OFF_EDG    600288ull            // 600000 x uint2 {src, scale} = 1,200,000 slots
#define OFF_XH     1800288ull           // half[N][128] = 3,200,000 slots
#define OFF_AGGH   5000288ull           // half[N][384] = 9,600,000 slots ; reused as z
#define OFF_H1H    14600288ull          // half[N][256] = 6,400,000 slots
#define OFF_U      21000288ull
#define OFF_V      21050288ull
#define OFF_BS1    21100288ull          // 256 floats
#define OFF_BS2    21100544ull          // 128 floats
#define OFF_BT1H   21100672ull          // half[256][384] = 49152 slots
#define OFF_BT2H   21149824ull          // half[384][256] = 49152 slots
#define SCRATCH_TOTAL 21198976ull

__device__ float g_scratch[SCRATCH_TOTAL];

// ================================================================ small kernels (exact R10)
__global__ void zero_kernel() {
    size_t i = (size_t)blockIdx.x * blockDim.x + threadIdx.x;
    if (i < ZERO_FLOATS / 4)
        reinterpret_cast<float4*>(g_scratch)[i] = make_float4(0.f, 0.f, 0.f, 0.f);
}

__global__ void pack_kernel(const float* __restrict__ W1, const float* __restrict__ W2,
                            const float* __restrict__ b1, const float* __restrict__ b2) {
    int i = blockIdx.x * blockDim.x + threadIdx.x;
    if (i < HH * RR * FF) {
        int h = i / (RR * FF);
        int k = i - h * (RR * FF);
        __half* bt = reinterpret_cast<__half*>(&g_scratch[OFF_BT1H]);
        bt[(size_t)h * (RR * FF) + k] = __float2half(W1[(size_t)k * HH + h]);
    } else if (i < 2 * HH * RR * FF) {
        int j = i - HH * RR * FF;
        int rf = j / HH;
        int h = j - rf * HH;
        int r = rf >> 7;
        int f = rf & 127;
        __half* bt = reinterpret_cast<__half*>(&g_scratch[OFF_BT2H]);
        bt[(size_t)rf * HH + h] = __float2half(W2[(size_t)r * HH * FF + (size_t)h * FF + f]);
    } else {
        int t = i - 2 * HH * RR * FF;
        if (t < HH) {
            g_scratch[OFF_BS1 + t] = b1[t] + b1[HH + t] + b1[2 * HH + t];
        } else if (t < HH + FF) {
            int h = t - HH;
            g_scratch[OFF_BS2 + h] = b2[h] + b2[FF + h] + b2[2 * FF + h];
        }
    }
}

__global__ void xh_kernel(const float* __restrict__ x) {
    int i = blockIdx.x * blockDim.x + threadIdx.x;
    if (i >= NN * FF / 8) return;
    const float4* x4 = reinterpret_cast<const float4*>(x);
    float4 a = x4[2 * i];
    float4 b = x4[2 * i + 1];
    __half2 h0 = __floats2half2_rn(a.x, a.y);
    __half2 h1 = __floats2half2_rn(a.z, a.w);
    __half2 h2 = __floats2half2_rn(b.x, b.y);
    __half2 h3 = __floats2half2_rn(b.z, b.w);
    uint4 o;
    o.x = *reinterpret_cast<unsigned*>(&h0);
    o.y = *reinterpret_cast<unsigned*>(&h1);
    o.z = *reinterpret_cast<unsigned*>(&h2);
    o.w = *reinterpret_cast<unsigned*>(&h3);
    reinterpret_cast<uint4*>(&g_scratch[OFF_XH])[i] = o;
}

__global__ void deg_kernel(const int* __restrict__ ei) {
    int i = blockIdx.x * blockDim.x + threadIdx.x;
    if (i >= RR * EE) return;
    int r = i / EE, e = i - r * EE;
    int src = ei[(size_t)r * 2 * EE + e];
    int dst = ei[(size_t)r * 2 * EE + EE + e];
    atomicAdd(&g_scratch[OFF_SC_OUT + (size_t)r * NN + src], 1.f);
    atomicAdd(&g_scratch[OFF_SC_IN  + (size_t)r * NN + dst], 1.f);
}

#define SCAN_B 1024
#define SCAN_NBLK ((NBINS + SCAN_B - 1) / SCAN_B)   // 147

__global__ void scanA_kernel() {
    __shared__ int sm[SCAN_B];
    int tid = threadIdx.x;
    int i = blockIdx.x * SCAN_B + tid;
    int v = (i < NBINS) ? (int)g_scratch[OFF_SC_IN + i] : 0;
    sm[tid] = v;
    __syncthreads();
    for (int off = 1; off < SCAN_B; off <<= 1) {
        int t = (tid >= off) ? sm[tid - off] : 0;
        __syncthreads();
        sm[tid] += t;
        __syncthreads();
    }
    if (i < NBINS)
        reinterpret_cast<int*>(g_scratch)[OFF_OFFSET + i] = sm[tid] - v;
    if (tid == SCAN_B - 1)
        reinterpret_cast<int*>(g_scratch)[OFF_BLKSUM + blockIdx.x] = sm[tid];
}

__global__ void scanB_kernel() {
    __shared__ int sm[256];
    int tid = threadIdx.x;
    int* bs = reinterpret_cast<int*>(g_scratch) + OFF_BLKSUM;
    int v = (tid < SCAN_NBLK) ? bs[tid] : 0;
    sm[tid] = v;
    __syncthreads();
    for (int off = 1; off < 256; off <<= 1) {
        int t = (tid >= off) ? sm[tid - off] : 0;
        __syncthreads();
        sm[tid] += t;
        __syncthreads();
    }
    if (tid < SCAN_NBLK) bs[tid] = sm[tid] - v;
}

__global__ void scanC_kernel() {
    int i = blockIdx.x * blockDim.x + threadIdx.x;
    if (i >= NBINS) return;
    int* ip = reinterpret_cast<int*>(g_scratch);
    ip[OFF_OFFSET + i] += ip[OFF_BLKSUM + i / SCAN_B];
}

__global__ void place_kernel(const int* __restrict__ ei) {
    int i = blockIdx.x * blockDim.x + threadIdx.x;
    if (i >= RR * EE) return;
    int r = i / EE, e = i - r * EE;
    int src = ei[(size_t)r * 2 * EE + e];
    int dst = ei[(size_t)r * 2 * EE + EE + e];
    float dout = g_scratch[OFF_SC_OUT + (size_t)r * NN + src];
    float din  = g_scratch[OFF_SC_IN  + (size_t)r * NN + dst];
    float s = rsqrtf(fmaxf(dout, 1.f)) * rsqrtf(fmaxf(din, 1.f));
    int bin = r * NN + dst;
    int* ip = reinterpret_cast<int*>(g_scratch);
    int pos = ip[OFF_OFFSET + bin] + atomicAdd(&ip[OFF_CURSOR + bin], 1);
    uint2* edg = reinterpret_cast<uint2*>(&g_scratch[OFF_EDG]);
    uint2 rec;
    rec.x = (unsigned)src;
    rec.y = __float_as_uint(s);
    edg[pos] = rec;
}

// ================================================================ gather helper (inline fn)
__device__ __forceinline__ void gfma(float4& acc, float c, uint2 wv) {
    float2 fa = __half22float2(*reinterpret_cast<__half2*>(&wv.x));
    float2 fb = __half22float2(*reinterpret_cast<__half2*>(&wv.y));
    acc.x = fmaf(c, fa.x, acc.x);
    acc.y = fmaf(c, fa.y, acc.y);
    acc.z = fmaf(c, fb.x, acc.z);
    acc.w = fmaf(c, fb.y, acc.w);
}

// ================================================================ gather layer 1 (exact R10: warp-per-dst, unroll-2)
__global__ void gather1_kernel() {
    int dst = (blockIdx.x * blockDim.x + threadIdx.x) >> 5;
    int lane = threadIdx.x & 31;
    if (dst >= NN) return;
    const int* ip = reinterpret_cast<const int*>(g_scratch);
    const uint2* edg = reinterpret_cast<const uint2*>(&g_scratch[OFF_EDG]);
    const __half* xh = reinterpret_cast<const __half*>(&g_scratch[OFF_XH]);
    __half* aggh = reinterpret_cast<__half*>(&g_scratch[OFF_AGGH]);
    #pragma unroll
    for (int r = 0; r < RR; r++) {
        int bin = r * NN + dst;
        int st = ip[OFF_OFFSET + bin];
        int cnt = ip[OFF_CURSOR + bin];
        float4 a0 = make_float4(0.f, 0.f, 0.f, 0.f);
        float4 a1 = make_float4(0.f, 0.f, 0.f, 0.f);
        int p = 0;
        for (; p + 2 <= cnt; p += 2) {
            uint2 e0 = edg[st + p];
            uint2 e1 = edg[st + p + 1];
            uint2 w0 = *reinterpret_cast<const uint2*>(xh + (size_t)e0.x * FF + lane * 4);
            uint2 w1 = *reinterpret_cast<const uint2*>(xh + (size_t)e1.x * FF + lane * 4);
            gfma(a0, __uint_as_float(e0.y), w0);
            gfma(a1, __uint_as_float(e1.y), w1);
        }
        if (p < cnt) {
            uint2 e0 = edg[st + p];
            uint2 w0 = *reinterpret_cast<const uint2*>(xh + (size_t)e0.x * FF + lane * 4);
            gfma(a0, __uint_as_float(e0.y), w0);
        }
        a0.x += a1.x; a0.y += a1.y; a0.z += a1.z; a0.w += a1.w;
        __half2 h01 = __floats2half2_rn(a0.x, a0.y);
        __half2 h23 = __floats2half2_rn(a0.z, a0.w);
        uint2 st2;
        st2.x = *reinterpret_cast<unsigned*>(&h01);
        st2.y = *reinterpret_cast<unsigned*>(&h23);
        *reinterpret_cast<uint2*>(aggh + (size_t)dst * 384 + r * FF + lane * 4) = st2;
    }
}

// ================================================================ gather layer 2 + uv (exact R10)
__global__ void gather2_uv_kernel(const float* __restrict__ Wlin) {
    int dst = (blockIdx.x * blockDim.x + threadIdx.x) >> 5;
    int lane = threadIdx.x & 31;
    if (dst >= NN) return;
    const int* ip = reinterpret_cast<const int*>(g_scratch);
    const uint2* edg = reinterpret_cast<const uint2*>(&g_scratch[OFF_EDG]);
    const __half* zh = reinterpret_cast<const __half*>(&g_scratch[OFF_AGGH]);
    float4 a0 = make_float4(0.f, 0.f, 0.f, 0.f);
    float4 a1 = make_float4(0.f, 0.f, 0.f, 0.f);
    #pragma unroll
    for (int r = 0; r < RR; r++) {
        int bin = r * NN + dst;
        int st = ip[OFF_OFFSET + bin];
        int cnt = ip[OFF_CURSOR + bin];
        int p = 0;
        for (; p + 2 <= cnt; p += 2) {
            uint2 e0 = edg[st + p];
            uint2 e1 = edg[st + p + 1];
            uint2 w0 = *reinterpret_cast<const uint2*>(zh + (size_t)e0.x * 384 + r * FF + lane * 4);
            uint2 w1 = *reinterpret_cast<const uint2*>(zh + (size_t)e1.x * 384 + r * FF + lane * 4);
            gfma(a0, __uint_as_float(e0.y), w0);
            gfma(a1, __uint_as_float(e1.y), w1);
        }
        if (p < cnt) {
            uint2 e0 = edg[st + p];
            uint2 w0 = *reinterpret_cast<const uint2*>(zh + (size_t)e0.x * 384 + r * FF + lane * 4);
            gfma(a0, __uint_as_float(e0.y), w0);
        }
    }
    a0.x += a1.x; a0.y += a1.y; a0.z += a1.z; a0.w += a1.w;
    const float inv3 = (1.f / 3.f);
    float4 bb = *reinterpret_cast<const float4*>(&g_scratch[OFF_BS2 + lane * 4]);
    a0.x = fmaxf((a0.x + bb.x) * inv3, 0.f);
    a0.y = fmaxf((a0.y + bb.y) * inv3, 0.f);
    a0.z = fmaxf((a0.z + bb.z) * inv3, 0.f);
    a0.w = fmaxf((a0.w + bb.w) * inv3, 0.f);
    const float4* wv = reinterpret_cast<const float4*>(Wlin);
    float4 wl = wv[lane];
    float4 wh = wv[32 + lane];
    float su = a0.x * wl.x + a0.y * wl.y + a0.z * wl.z + a0.w * wl.w;
    float sv = a0.x * wh.x + a0.y * wh.y + a0.z * wh.z + a0.w * wh.w;
    #pragma unroll
    for (int o = 16; o > 0; o >>= 1) {
        su += __shfl_down_sync(0xffffffffu, su, o);
        sv += __shfl_down_sync(0xffffffffu, sv, o);
    }
    if (lane == 0) {
        g_scratch[OFF_U + dst] = su;
        g_scratch[OFF_V + dst] = sv;
    }
}

// ================================================================ fp16 tensor-core GEMM
// BM=128, BN=128, BK=32; cp.async double-buffered; LDSM fragment loads (only change vs R10)
#define BM 128
#define BN 128
#define BK 32
#define BKP 40   // +8 halves pad: 80B row stride -> conflict-free LDSM phases

__device__ __forceinline__ void mma_fp16(float* d, const unsigned* a, const unsigned* b) {
    asm volatile("mma.sync.aligned.m16n8k16.row.col.f32.f16.f16.f32 "
                 "{%0,%1,%2,%3}, {%4,%5,%6,%7}, {%8,%9}, {%0,%1,%2,%3};"
                 : "+f"(d[0]), "+f"(d[1]), "+f"(d[2]), "+f"(d[3])
                 : "r"(a[0]), "r"(a[1]), "r"(a[2]), "r"(a[3]),
                   "r"(b[0]), "r"(b[1]));
}

__device__ __forceinline__ void ldsm_x4(unsigned* r, uint32_t addr) {
    asm volatile("ldmatrix.sync.aligned.m8n8.x4.shared.b16 {%0,%1,%2,%3}, [%4];"
                 : "=r"(r[0]), "=r"(r[1]), "=r"(r[2]), "=r"(r[3]) : "r"(addr));
}

__device__ __forceinline__ uint32_t smem_cast(const void* p) {
    uint32_t a;
    asm("{ .reg .u64 t; cvta.to.shared.u64 t, %1; cvt.u32.u64 %0, t; }" : "=r"(a) : "l"(p));
    return a;
}

__device__ __forceinline__ void cp_async16(uint32_t dst, const void* src, int src_bytes) {
    asm volatile("cp.async.ca.shared.global [%0], [%1], 16, %2;"
                 :: "r"(dst), "l"(src), "r"(src_bytes) : "memory");
}
#define CP_COMMIT() asm volatile("cp.async.commit_group;" ::: "memory")
#define CP_WAIT1()  asm volatile("cp.async.wait_group 1;" ::: "memory")
#define CP_WAIT0()  asm volatile("cp.async.wait_group 0;" ::: "memory")

__global__ __launch_bounds__(256) void gemm_fp16_kernel(
    const __half* __restrict__ A, const __half* __restrict__ Bt,
    const float* __restrict__ bias, __half* __restrict__ C,
    int M, int K, int Ncol, int doRelu, float scale)
{
    __shared__ __half As[2][BM][BKP];
    __shared__ __half Bs[2][BN][BKP];

    int tid = threadIdx.x;
    int warp = tid >> 5;
    int lane = tid & 31;
    int wr = warp >> 1;        // m offset 32*wr
    int wc = warp & 1;         // n offset 64*wc
    int bm = blockIdx.y * BM, bn = blockIdx.x * BN;
    int tg = lane >> 2;
    int tq = lane & 3;

    // LDSM per-lane addressing: quad q -> rows +((q&1)*8), cols +((q>>1)*8)
    int quad = lane >> 3;
    int ldrow = (lane & 7) + ((quad & 1) << 3);
    int ldcol = (quad >> 1) << 3;

    float acc[2][8][4];
    #pragma unroll
    for (int i = 0; i < 2; i++)
        #pragma unroll
        for (int j = 0; j < 8; j++)
            #pragma unroll
            for (int q = 0; q < 4; q++) acc[i][j][q] = 0.f;

    uint32_t as_base = smem_cast(&As[0][0][0]);
    uint32_t bs_base = smem_cast(&Bs[0][0][0]);
    const uint32_t BUFB = BM * BKP * 2;

    int nT = K / BK;

    #define LOAD_TILE(k0, buf) do {                                              \
        _Pragma("unroll")                                                        \
        for (int it = 0; it < 2; it++) {                                         \
            int ch = tid + it * 256;                                             \
            int row = ch >> 2, c8 = ch & 3;                                      \
            int m = bm + row;                                                    \
            int mc = (m < M) ? m : 0;                                            \
            cp_async16(as_base + (buf) * BUFB + row * (BKP * 2) + c8 * 16,       \
                       A + (size_t)mc * K + (k0) + c8 * 8, (m < M) ? 16 : 0);    \
        }                                                                        \
        _Pragma("unroll")                                                        \
        for (int it = 0; it < 2; it++) {                                         \
            int ch = tid + it * 256;                                             \
            int row = ch >> 2, c8 = ch & 3;                                      \
            cp_async16(bs_base + (buf) * BUFB + row * (BKP * 2) + c8 * 16,       \
                       Bt + (size_t)(bn + row) * K + (k0) + c8 * 8, 16);         \
        }                                                                        \
    } while (0)

    LOAD_TILE(0, 0);
    CP_COMMIT();

    for (int t = 0; t < nT; t++) {
        int buf = t & 1;
        if (t + 1 < nT) {
            LOAD_TILE((t + 1) * BK, buf ^ 1);
            CP_COMMIT();
            CP_WAIT1();
        } else {
            CP_WAIT0();
        }
        __syncthreads();

        #pragma unroll
        for (int kk = 0; kk < BK; kk += 16) {
            unsigned af[2][4], bf[8][2];
            #pragma unroll
            for (int i = 0; i < 2; i++) {
                int mb = wr * 32 + i * 16;
                uint32_t addr = as_base + (uint32_t)buf * BUFB
                              + (uint32_t)((mb + ldrow) * (BKP * 2) + (kk + ldcol) * 2);
                ldsm_x4(af[i], addr);
            }
            #pragma unroll
            for (int j2 = 0; j2 < 4; j2++) {
                int nb = wc * 64 + j2 * 16;
                uint32_t addr = bs_base + (uint32_t)buf * BUFB
                              + (uint32_t)((nb + ldrow) * (BKP * 2) + (kk + ldcol) * 2);
                unsigned tb[4];
                ldsm_x4(tb, addr);
                bf[2 * j2][0]     = tb[0];
                bf[2 * j2 + 1][0] = tb[1];
                bf[2 * j2][1]     = tb[2];
                bf[2 * j2 + 1][1] = tb[3];
            }
            #pragma unroll
            for (int i = 0; i < 2; i++)
                #pragma unroll
                for (int j = 0; j < 8; j++)
                    mma_fp16(acc[i][j], af[i], bf[j]);
        }
        __syncthreads();
    }

    #pragma unroll
    for (int i = 0; i < 2; i++) {
        #pragma unroll
        for (int j = 0; j < 8; j++) {
            int col = bn + wc * 64 + j * 8 + tq * 2;
            float b0 = 0.f, b1 = 0.f;
            if (bias) { b0 = bias[col]; b1 = bias[col + 1]; }
            #pragma unroll
            for (int h = 0; h < 2; h++) {
                int row = bm + wr * 32 + i * 16 + tg + h * 8;
                if (row < M) {
                    float o0 = (acc[i][j][2 * h + 0] + b0) * scale;
                    float o1 = (acc[i][j][2 * h + 1] + b1) * scale;
                    if (doRelu) { o0 = fmaxf(o0, 0.f); o1 = fmaxf(o1, 0.f); }
                    *reinterpret_cast<__half2*>(C + (size_t)row * Ncol + col) =
                        __floats2half2_rn(o0, o1);
                }
            }
        }
    }
}

// ================================================================ pair head
__global__ void pairs_kernel(const int* __restrict__ ei, const int* __restrict__ np,
                             const float* __restrict__ blin, float* __restrict__ out) {
    int i = blockIdx.x * blockDim.x + threadIdx.x;
    if (i >= NPAIRS) return;
    int src, dst;
    if (i < RR * EE) {
        int r = i / EE, e = i - r * EE;
        src = ei[(size_t)r * 2 * EE + e];
        dst = ei[(size_t)r * 2 * EE + EE + e];
    } else {
        int j = i - RR * EE;
        src = np[2 * j];
        dst = np[2 * j + 1];
    }
    float z = g_scratch[OFF_U + src] + g_scratch[OFF_V + dst] + blin[0];
    out[i] = 1.f / (1.f + expf(-z));
}

// ================================================================ launch (exact R10 structure)
extern "C" void kernel_launch(void* const* d_in, const int* in_sizes, int n_in,
                              void* d_out, int out_size) {
    const float* x    = (const float*)d_in[0];
    const int*   ei   = (const int*)  d_in[1];
    const int*   np   = (const int*)  d_in[2];
    const float* W1   = (const float*)d_in[3];
    const float* b1   = (const float*)d_in[4];
    const float* W2   = (const float*)d_in[5];
    const float* b2   = (const float*)d_in[6];
    const float* Wlin = (const float*)d_in[7];
    const float* blin = (const float*)d_in[8];
    float* out = (float*)d_out;

    void* base = nullptr;
    cudaGetSymbolAddress(&base, g_scratch);
    float* fb = (float*)base;
    __half* aggh = (__half*)(fb + OFF_AGGH);
    __half* h1h  = (__half*)(fb + OFF_H1H);
    __half* bt1h = (__half*)(fb + OFF_BT1H);
    __half* bt2h = (__half*)(fb + OFF_BT2H);
    float* bs1   = fb + OFF_BS1;

    // 1. zero scales + cursors
    zero_kernel<<<(unsigned)((ZERO_FLOATS / 4 + 255) / 256), 256>>>();
    // 2. weight/bias pack + x->half
    pack_kernel<<<(2 * HH * RR * FF + HH + FF + 255) / 256, 256>>>(W1, W2, b1, b2);
    xh_kernel<<<(NN * FF / 8 + 255) / 256, 256>>>(x);
    // 3. degrees
    deg_kernel<<<(RR * EE + 255) / 256, 256>>>(ei);
    // 4. CSR offsets
    scanA_kernel<<<SCAN_NBLK, SCAN_B>>>();
    scanB_kernel<<<1, 256>>>();
    scanC_kernel<<<(NBINS + 255) / 256, 256>>>();
    // 5. edge placement (rsqrt folded)
    place_kernel<<<(RR * EE + 255) / 256, 256>>>(ei);
    // 6. layer-1 gather
    gather1_kernel<<<(NN * 32 + 255) / 256, 256>>>();
    // 7. GEMM1: h1 = relu((agg @ W1 + bs1)/3)
    gemm_fp16_kernel<<<dim3(HH / BN, (NN + BM - 1) / BM), 256>>>(
        aggh, bt1h, bs1, h1h, NN, RR * FF, HH, 1, 1.f / 3.f);
    // 8. GEMM2: z = h1 @ W2P -> reuse aggh
    gemm_fp16_kernel<<<dim3((RR * FF) / BN, (NN + BM - 1) / BM), 256>>>(
        h1h, bt2h, nullptr, aggh, NN, HH, RR * FF, 0, 1.f);
    // 9. layer-2 gather + u/v
    gather2_uv_kernel<<<(NN * 32 + 255) / 256, 256>>>(Wlin);
    // 10. pair outputs
    pairs_kernel<<<(NPAIRS + 255) / 256, 256>>>(ei, np, blin, out);
}

// round 16
// speedup vs baseline: 1.0803x; 1.0219x over previous
#include <cuda_runtime.h>
#include <cuda_fp16.h>
#include <math.h>
#include <stdint.h>

// Problem constants (fixed shapes)
#define NN 50000
#define EE 200000
#define RR 3
#define FF 128
#define HH 256
#define PP 100000
#define NPAIRS (RR*EE + PP)   // 700000
#define NBINS (RR*NN)         // 150000

// scratch layout (float slots) — [zeroed region | persistent region]
#define OFF_SC_OUT 0ull                 // 150000 raw out-degree counts
#define OFF_SC_IN  150000ull            // 150000 raw in-degree counts
#define OFF_CURSOR 300000ull            // 150016 ints
#define ZERO_FLOATS 450016ull
#define OFF_OFFSET 450016ull            // 150016 ints
#define OFF_BLKSUM 600032ull            // 256 ints
#define OFF_EDG    600288ull            // 600000 x uint2 {src, scale} = 1,200,000 slots
#define OFF_XH     1800288ull           // half[N][128] = 3,200,000 slots
#define OFF_AGGH   5000288ull           // half[N][384] = 9,600,000 slots ; reused as z
#define OFF_H1H    14600288ull          // half[N][256] = 6,400,000 slots
#define OFF_U      21000288ull
#define OFF_V      21050288ull
#define OFF_BS1    21100288ull          // 256 floats
#define OFF_BS2    21100544ull          // 128 floats
#define OFF_BT1H   21100672ull          // half[256][384] = 49152 slots
#define OFF_BT2H   21149824ull          // half[384][256] = 49152 slots
#define SCRATCH_TOTAL 21198976ull

__device__ float g_scratch[SCRATCH_TOTAL];

// ================================================================ small kernels (exact R15)
__global__ void zero_kernel() {
    size_t i = (size_t)blockIdx.x * blockDim.x + threadIdx.x;
    if (i < ZERO_FLOATS / 4)
        reinterpret_cast<float4*>(g_scratch)[i] = make_float4(0.f, 0.f, 0.f, 0.f);
}

__global__ void pack_kernel(const float* __restrict__ W1, const float* __restrict__ W2,
                            const float* __restrict__ b1, const float* __restrict__ b2) {
    int i = blockIdx.x * blockDim.x + threadIdx.x;
    if (i < HH * RR * FF) {
        int h = i / (RR * FF);
        int k = i - h * (RR * FF);
        __half* bt = reinterpret_cast<__half*>(&g_scratch[OFF_BT1H]);
        bt[(size_t)h * (RR * FF) + k] = __float2half(W1[(size_t)k * HH + h]);
    } else if (i < 2 * HH * RR * FF) {
        int j = i - HH * RR * FF;
        int rf = j / HH;
        int h = j - rf * HH;
        int r = rf >> 7;
        int f = rf & 127;
        __half* bt = reinterpret_cast<__half*>(&g_scratch[OFF_BT2H]);
        bt[(size_t)rf * HH + h] = __float2half(W2[(size_t)r * HH * FF + (size_t)h * FF + f]);
    } else {
        int t = i - 2 * HH * RR * FF;
        if (t < HH) {
            g_scratch[OFF_BS1 + t] = b1[t] + b1[HH + t] + b1[2 * HH + t];
        } else if (t < HH + FF) {
            int h = t - HH;
            g_scratch[OFF_BS2 + h] = b2[h] + b2[FF + h] + b2[2 * FF + h];
        }
    }
}

__global__ void xh_kernel(const float* __restrict__ x) {
    int i = blockIdx.x * blockDim.x + threadIdx.x;
    if (i >= NN * FF / 8) return;
    const float4* x4 = reinterpret_cast<const float4*>(x);
    float4 a = x4[2 * i];
    float4 b = x4[2 * i + 1];
    __half2 h0 = __floats2half2_rn(a.x, a.y);
    __half2 h1 = __floats2half2_rn(a.z, a.w);
    __half2 h2 = __floats2half2_rn(b.x, b.y);
    __half2 h3 = __floats2half2_rn(b.z, b.w);
    uint4 o;
    o.x = *reinterpret_cast<unsigned*>(&h0);
    o.y = *reinterpret_cast<unsigned*>(&h1);
    o.z = *reinterpret_cast<unsigned*>(&h2);
    o.w = *reinterpret_cast<unsigned*>(&h3);
    reinterpret_cast<uint4*>(&g_scratch[OFF_XH])[i] = o;
}

__global__ void deg_kernel(const int* __restrict__ ei) {
    int i = blockIdx.x * blockDim.x + threadIdx.x;
    if (i >= RR * EE) return;
    int r = i / EE, e = i - r * EE;
    int src = ei[(size_t)r * 2 * EE + e];
    int dst = ei[(size_t)r * 2 * EE + EE + e];
    atomicAdd(&g_scratch[OFF_SC_OUT + (size_t)r * NN + src], 1.f);
    atomicAdd(&g_scratch[OFF_SC_IN  + (size_t)r * NN + dst], 1.f);
}

#define SCAN_B 1024
#define SCAN_NBLK ((NBINS + SCAN_B - 1) / SCAN_B)   // 147

__global__ void scanA_kernel() {
    __shared__ int sm[SCAN_B];
    int tid = threadIdx.x;
    int i = blockIdx.x * SCAN_B + tid;
    int v = (i < NBINS) ? (int)g_scratch[OFF_SC_IN + i] : 0;
    sm[tid] = v;
    __syncthreads();
    for (int off = 1; off < SCAN_B; off <<= 1) {
        int t = (tid >= off) ? sm[tid - off] : 0;
        __syncthreads();
        sm[tid] += t;
        __syncthreads();
    }
    if (i < NBINS)
        reinterpret_cast<int*>(g_scratch)[OFF_OFFSET + i] = sm[tid] - v;
    if (tid == SCAN_B - 1)
        reinterpret_cast<int*>(g_scratch)[OFF_BLKSUM + blockIdx.x] = sm[tid];
}

__global__ void scanB_kernel() {
    __shared__ int sm[256];
    int tid = threadIdx.x;
    int* bs = reinterpret_cast<int*>(g_scratch) + OFF_BLKSUM;
    int v = (tid < SCAN_NBLK) ? bs[tid] : 0;
    sm[tid] = v;
    __syncthreads();
    for (int off = 1; off < 256; off <<= 1) {
        int t = (tid >= off) ? sm[tid - off] : 0;
        __syncthreads();
        sm[tid] += t;
        __syncthreads();
    }
    if (tid < SCAN_NBLK) bs[tid] = sm[tid] - v;
}

__global__ void scanC_kernel() {
    int i = blockIdx.x * blockDim.x + threadIdx.x;
    if (i >= NBINS) return;
    int* ip = reinterpret_cast<int*>(g_scratch);
    ip[OFF_OFFSET + i] += ip[OFF_BLKSUM + i / SCAN_B];
}

__global__ void place_kernel(const int* __restrict__ ei) {
    int i = blockIdx.x * blockDim.x + threadIdx.x;
    if (i >= RR * EE) return;
    int r = i / EE, e = i - r * EE;
    int src = ei[(size_t)r * 2 * EE + e];
    int dst = ei[(size_t)r * 2 * EE + EE + e];
    float dout = g_scratch[OFF_SC_OUT + (size_t)r * NN + src];
    float din  = g_scratch[OFF_SC_IN  + (size_t)r * NN + dst];
    float s = rsqrtf(fmaxf(dout, 1.f)) * rsqrtf(fmaxf(din, 1.f));
    int bin = r * NN + dst;
    int* ip = reinterpret_cast<int*>(g_scratch);
    int pos = ip[OFF_OFFSET + bin] + atomicAdd(&ip[OFF_CURSOR + bin], 1);
    uint2* edg = reinterpret_cast<uint2*>(&g_scratch[OFF_EDG]);
    uint2 rec;
    rec.x = (unsigned)src;
    rec.y = __float_as_uint(s);
    edg[pos] = rec;
}

// ================================================================ gather helper (inline fn)
__device__ __forceinline__ void gfma(float4& acc, float c, uint2 wv) {
    float2 fa = __half22float2(*reinterpret_cast<__half2*>(&wv.x));
    float2 fb = __half22float2(*reinterpret_cast<__half2*>(&wv.y));
    acc.x = fmaf(c, fa.x, acc.x);
    acc.y = fmaf(c, fa.y, acc.y);
    acc.z = fmaf(c, fb.x, acc.z);
    acc.w = fmaf(c, fb.y, acc.w);
}

// ================================================================ gather layer 1 (warp-per-dst, unroll-2)
__global__ void gather1_kernel() {
    int dst = (blockIdx.x * blockDim.x + threadIdx.x) >> 5;
    int lane = threadIdx.x & 31;
    if (dst >= NN) return;
    const int* ip = reinterpret_cast<const int*>(g_scratch);
    const uint2* edg = reinterpret_cast<const uint2*>(&g_scratch[OFF_EDG]);
    const __half* xh = reinterpret_cast<const __half*>(&g_scratch[OFF_XH]);
    __half* aggh = reinterpret_cast<__half*>(&g_scratch[OFF_AGGH]);
    #pragma unroll
    for (int r = 0; r < RR; r++) {
        int bin = r * NN + dst;
        int st = ip[OFF_OFFSET + bin];
        int cnt = ip[OFF_CURSOR + bin];
        float4 a0 = make_float4(0.f, 0.f, 0.f, 0.f);
        float4 a1 = make_float4(0.f, 0.f, 0.f, 0.f);
        int p = 0;
        for (; p + 2 <= cnt; p += 2) {
            uint2 e0 = edg[st + p];
            uint2 e1 = edg[st + p + 1];
            uint2 w0 = *reinterpret_cast<const uint2*>(xh + (size_t)e0.x * FF + lane * 4);
            uint2 w1 = *reinterpret_cast<const uint2*>(xh + (size_t)e1.x * FF + lane * 4);
            gfma(a0, __uint_as_float(e0.y), w0);
            gfma(a1, __uint_as_float(e1.y), w1);
        }
        if (p < cnt) {
            uint2 e0 = edg[st + p];
            uint2 w0 = *reinterpret_cast<const uint2*>(xh + (size_t)e0.x * FF + lane * 4);
            gfma(a0, __uint_as_float(e0.y), w0);
        }
        a0.x += a1.x; a0.y += a1.y; a0.z += a1.z; a0.w += a1.w;
        __half2 h01 = __floats2half2_rn(a0.x, a0.y);
        __half2 h23 = __floats2half2_rn(a0.z, a0.w);
        uint2 st2;
        st2.x = *reinterpret_cast<unsigned*>(&h01);
        st2.y = *reinterpret_cast<unsigned*>(&h23);
        *reinterpret_cast<uint2*>(aggh + (size_t)dst * 384 + r * FF + lane * 4) = st2;
    }
}

// ================================================================ gather layer 2 + uv
__global__ void gather2_uv_kernel(const float* __restrict__ Wlin) {
    int dst = (blockIdx.x * blockDim.x + threadIdx.x) >> 5;
    int lane = threadIdx.x & 31;
    if (dst >= NN) return;
    const int* ip = reinterpret_cast<const int*>(g_scratch);
    const uint2* edg = reinterpret_cast<const uint2*>(&g_scratch[OFF_EDG]);
    const __half* zh = reinterpret_cast<const __half*>(&g_scratch[OFF_AGGH]);
    float4 a0 = make_float4(0.f, 0.f, 0.f, 0.f);
    float4 a1 = make_float4(0.f, 0.f, 0.f, 0.f);
    #pragma unroll
    for (int r = 0; r < RR; r++) {
        int bin = r * NN + dst;
        int st = ip[OFF_OFFSET + bin];
        int cnt = ip[OFF_CURSOR + bin];
        int p = 0;
        for (; p + 2 <= cnt; p += 2) {
            uint2 e0 = edg[st + p];
            uint2 e1 = edg[st + p + 1];
            uint2 w0 = *reinterpret_cast<const uint2*>(zh + (size_t)e0.x * 384 + r * FF + lane * 4);
            uint2 w1 = *reinterpret_cast<const uint2*>(zh + (size_t)e1.x * 384 + r * FF + lane * 4);
            gfma(a0, __uint_as_float(e0.y), w0);
            gfma(a1, __uint_as_float(e1.y), w1);
        }
        if (p < cnt) {
            uint2 e0 = edg[st + p];
            uint2 w0 = *reinterpret_cast<const uint2*>(zh + (size_t)e0.x * 384 + r * FF + lane * 4);
            gfma(a0, __uint_as_float(e0.y), w0);
        }
    }
    a0.x += a1.x; a0.y += a1.y; a0.z += a1.z; a0.w += a1.w;
    const float inv3 = (1.f / 3.f);
    float4 bb = *reinterpret_cast<const float4*>(&g_scratch[OFF_BS2 + lane * 4]);
    a0.x = fmaxf((a0.x + bb.x) * inv3, 0.f);
    a0.y = fmaxf((a0.y + bb.y) * inv3, 0.f);
    a0.z = fmaxf((a0.z + bb.z) * inv3, 0.f);
    a0.w = fmaxf((a0.w + bb.w) * inv3, 0.f);
    const float4* wv = reinterpret_cast<const float4*>(Wlin);
    float4 wl = wv[lane];
    float4 wh = wv[32 + lane];
    float su = a0.x * wl.x + a0.y * wl.y + a0.z * wl.z + a0.w * wl.w;
    float sv = a0.x * wh.x + a0.y * wh.y + a0.z * wh.z + a0.w * wh.w;
    #pragma unroll
    for (int o = 16; o > 0; o >>= 1) {
        su += __shfl_down_sync(0xffffffffu, su, o);
        sv += __shfl_down_sync(0xffffffffu, sv, o);
    }
    if (lane == 0) {
        g_scratch[OFF_U + dst] = su;
        g_scratch[OFF_V + dst] = sv;
    }
}

// ================================================================ fp16 tensor-core GEMM
// BM=128, BN=128, BK=32; cp.async 3-STAGE ring (one sync per tile); LDSM fragments
#define BM 128
#define BN 128
#define BK 32
#define BKP 40   // +8 halves pad: 80B row stride -> conflict-free LDSM phases

__device__ __forceinline__ void mma_fp16(float* d, const unsigned* a, const unsigned* b) {
    asm volatile("mma.sync.aligned.m16n8k16.row.col.f32.f16.f16.f32 "
                 "{%0,%1,%2,%3}, {%4,%5,%6,%7}, {%8,%9}, {%0,%1,%2,%3};"
                 : "+f"(d[0]), "+f"(d[1]), "+f"(d[2]), "+f"(d[3])
                 : "r"(a[0]), "r"(a[1]), "r"(a[2]), "r"(a[3]),
                   "r"(b[0]), "r"(b[1]));
}

__device__ __forceinline__ void ldsm_x4(unsigned* r, uint32_t addr) {
    asm volatile("ldmatrix.sync.aligned.m8n8.x4.shared.b16 {%0,%1,%2,%3}, [%4];"
                 : "=r"(r[0]), "=r"(r[1]), "=r"(r[2]), "=r"(r[3]) : "r"(addr));
}

__device__ __forceinline__ uint32_t smem_cast(const void* p) {
    uint32_t a;
    asm("{ .reg .u64 t; cvta.to.shared.u64 t, %1; cvt.u32.u64 %0, t; }" : "=r"(a) : "l"(p));
    return a;
}

__device__ __forceinline__ void cp_async16(uint32_t dst, const void* src, int src_bytes) {
    asm volatile("cp.async.ca.shared.global [%0], [%1], 16, %2;"
                 :: "r"(dst), "l"(src), "r"(src_bytes) : "memory");
}
#define CP_COMMIT() asm volatile("cp.async.commit_group;" ::: "memory")
#define CP_WAIT1()  asm volatile("cp.async.wait_group 1;" ::: "memory")
#define CP_WAIT0()  asm volatile("cp.async.wait_group 0;" ::: "memory")

__global__ __launch_bounds__(256) void gemm_fp16_kernel(
    const __half* __restrict__ A, const __half* __restrict__ Bt,
    const float* __restrict__ bias, __half* __restrict__ C,
    int M, int K, int Ncol, int doRelu, float scale)
{
    __shared__ __half As[3][BM][BKP];
    __shared__ __half Bs[3][BN][BKP];

    int tid = threadIdx.x;
    int warp = tid >> 5;
    int lane = tid & 31;
    int wr = warp >> 1;        // m offset 32*wr
    int wc = warp & 1;         // n offset 64*wc
    int bm = blockIdx.y * BM, bn = blockIdx.x * BN;
    int tg = lane >> 2;
    int tq = lane & 3;

    // LDSM per-lane addressing: quad q -> rows +((q&1)*8), cols +((q>>1)*8)
    int quad = lane >> 3;
    int ldrow = (lane & 7) + ((quad & 1) << 3);
    int ldcol = (quad >> 1) << 3;

    float acc[2][8][4];
    #pragma unroll
    for (int i = 0; i < 2; i++)
        #pragma unroll
        for (int j = 0; j < 8; j++)
            #pragma unroll
            for (int q = 0; q < 4; q++) acc[i][j][q] = 0.f;

    uint32_t as_base = smem_cast(&As[0][0][0]);
    uint32_t bs_base = smem_cast(&Bs[0][0][0]);
    const uint32_t BUFB = BM * BKP * 2;

    int nT = K / BK;

    #define LOAD_TILE(k0, buf) do {                                              \
        _Pragma("unroll")                                                        \
        for (int it = 0; it < 2; it++) {                                         \
            int ch = tid + it * 256;                                             \
            int row = ch >> 2, c8 = ch & 3;                                      \
            int m = bm + row;                                                    \
            int mc = (m < M) ? m : 0;                                            \
            cp_async16(as_base + (buf) * BUFB + row * (BKP * 2) + c8 * 16,       \
                       A + (size_t)mc * K + (k0) + c8 * 8, (m < M) ? 16 : 0);    \
        }                                                                        \
        _Pragma("unroll")                                                        \
        for (int it = 0; it < 2; it++) {                                         \
            int ch = tid + it * 256;                                             \
            int row = ch >> 2, c8 = ch & 3;                                      \
            cp_async16(bs_base + (buf) * BUFB + row * (BKP * 2) + c8 * 16,       \
                       Bt + (size_t)(bn + row) * K + (k0) + c8 * 8, 16);         \
        }                                                                        \
    } while (0)

    // prologue: prefetch tiles 0 and 1 (each its own commit group)
    LOAD_TILE(0, 0);
    CP_COMMIT();
    if (nT > 1) {
        LOAD_TILE(BK, 1);
        CP_COMMIT();
    }

    int buf = 0;           // buffer holding tile t
    int nbuf = (nT > 1) ? 2 : 1;   // next free buffer index (tile t+2 target)
    for (int t = 0; t < nT; t++) {
        // wait until tile t's group is complete
        if (t + 1 < nT) { CP_WAIT1(); } else { CP_WAIT0(); }
        __syncthreads();   // loads visible to all; also orders prior compute vs upcoming overwrite

        // prefetch tile t+2 into the buffer freed by tile t-1
        if (t + 2 < nT) {
            LOAD_TILE((t + 2) * BK, nbuf);
            CP_COMMIT();
            nbuf = (nbuf == 2) ? 0 : nbuf + 1;
        }

        #pragma unroll
        for (int kk = 0; kk < BK; kk += 16) {
            unsigned af[2][4], bf[8][2];
            #pragma unroll
            for (int i = 0; i < 2; i++) {
                int mb = wr * 32 + i * 16;
                uint32_t addr = as_base + (uint32_t)buf * BUFB
                              + (uint32_t)((mb + ldrow) * (BKP * 2) + (kk + ldcol) * 2);
                ldsm_x4(af[i], addr);
            }
            #pragma unroll
            for (int j2 = 0; j2 < 4; j2++) {
                int nb = wc * 64 + j2 * 16;
                uint32_t addr = bs_base + (uint32_t)buf * BUFB
                              + (uint32_t)((nb + ldrow) * (BKP * 2) + (kk + ldcol) * 2);
                unsigned tb[4];
                ldsm_x4(tb, addr);
                bf[2 * j2][0]     = tb[0];
                bf[2 * j2 + 1][0] = tb[1];
                bf[2 * j2][1]     = tb[2];
                bf[2 * j2 + 1][1] = tb[3];
            }
            #pragma unroll
            for (int i = 0; i < 2; i++)
                #pragma unroll
                for (int j = 0; j < 8; j++)
                    mma_fp16(acc[i][j], af[i], bf[j]);
        }
        buf = (buf == 2) ? 0 : buf + 1;
    }

    #pragma unroll
    for (int i = 0; i < 2; i++) {
        #pragma unroll
        for (int j = 0; j < 8; j++) {
            int col = bn + wc * 64 + j * 8 + tq * 2;
            float b0 = 0.f, b1 = 0.f;
            if (bias) { b0 = bias[col]; b1 = bias[col + 1]; }
            #pragma unroll
            for (int h = 0; h < 2; h++) {
                int row = bm + wr * 32 + i * 16 + tg + h * 8;
                if (row < M) {
                    float o0 = (acc[i][j][2 * h + 0] + b0) * scale;
                    float o1 = (acc[i][j][2 * h + 1] + b1) * scale;
                    if (doRelu) { o0 = fmaxf(o0, 0.f); o1 = fmaxf(o1, 0.f); }
                    *reinterpret_cast<__half2*>(C + (size_t)row * Ncol + col) =
                        __floats2half2_rn(o0, o1);
                }
            }
        }
    }
}

// ================================================================ pair head
__global__ void pairs_kernel(const int* __restrict__ ei, const int* __restrict__ np,
                             const float* __restrict__ blin, float* __restrict__ out) {
    int i = blockIdx.x * blockDim.x + threadIdx.x;
    if (i >= NPAIRS) return;
    int src, dst;
    if (i < RR * EE) {
        int r = i / EE, e = i - r * EE;
        src = ei[(size_t)r * 2 * EE + e];
        dst = ei[(size_t)r * 2 * EE + EE + e];
    } else {
        int j = i - RR * EE;
        src = np[2 * j];
        dst = np[2 * j + 1];
    }
    float z = g_scratch[OFF_U + src] + g_scratch[OFF_V + dst] + blin[0];
    out[i] = 1.f / (1.f + expf(-z));
}

// ================================================================ launch
extern "C" void kernel_launch(void* const* d_in, const int* in_sizes, int n_in,
                              void* d_out, int out_size) {
    const float* x    = (const float*)d_in[0];
    const int*   ei   = (const int*)  d_in[1];
    const int*   np   = (const int*)  d_in[2];
    const float* W1   = (const float*)d_in[3];
    const float* b1   = (const float*)d_in[4];
    const float* W2   = (const float*)d_in[5];
    const float* b2   = (const float*)d_in[6];
    const float* Wlin = (const float*)d_in[7];
    const float* blin = (const float*)d_in[8];
    float* out = (float*)d_out;

    void* base = nullptr;
    cudaGetSymbolAddress(&base, g_scratch);
    float* fb = (float*)base;
    __half* aggh = (__half*)(fb + OFF_AGGH);
    __half* h1h  = (__half*)(fb + OFF_H1H);
    __half* bt1h = (__half*)(fb + OFF_BT1H);
    __half* bt2h = (__half*)(fb + OFF_BT2H);
    float* bs1   = fb + OFF_BS1;

    // 1. zero scales + cursors
    zero_kernel<<<(unsigned)((ZERO_FLOATS / 4 + 255) / 256), 256>>>();
    // 2. weight/bias pack + x->half
    pack_kernel<<<(2 * HH * RR * FF + HH + FF + 255) / 256, 256>>>(W1, W2, b1, b2);
    xh_kernel<<<(NN * FF / 8 + 255) / 256, 256>>>(x);
    // 3. degrees
    deg_kernel<<<(RR * EE + 255) / 256, 256>>>(ei);
    // 4. CSR offsets
    scanA_kernel<<<SCAN_NBLK, SCAN_B>>>();
    scanB_kernel<<<1, 256>>>();
    scanC_kernel<<<(NBINS + 255) / 256, 256>>>();
    // 5. edge placement (rsqrt folded)
    place_kernel<<<(RR * EE + 255) / 256, 256>>>(ei);
    // 6. layer-1 gather
    gather1_kernel<<<(NN * 32 + 255) / 256, 256>>>();
    // 7. GEMM1: h1 = relu((agg @ W1 + bs1)/3)
    gemm_fp16_kernel<<<dim3(HH / BN, (NN + BM - 1) / BM), 256>>>(
        aggh, bt1h, bs1, h1h, NN, RR * FF, HH, 1, 1.f / 3.f);
    // 8. GEMM2: z = h1 @ W2P -> reuse aggh
    gemm_fp16_kernel<<<dim3((RR * FF) / BN, (NN + BM - 1) / BM), 256>>>(
        h1h, bt2h, nullptr, aggh, NN, HH, RR * FF, 0, 1.f);
    // 9. layer-2 gather + u/v
    gather2_uv_kernel<<<(NN * 32 + 255) / 256, 256>>>(Wlin);
    // 10. pair outputs
    pairs_kernel<<<(NPAIRS + 255) / 256, 256>>>(ei, np, blin, out);
}